// round 5
// baseline (speedup 1.0000x reference)
#include <cuda_runtime.h>
#include <math.h>
#include <stdint.h>

#define TLEN  500
#define BATCH 32
#define DIN   1024
#define HID   1024
#define NT    4096      // 4 gates * HID
#define GRID_REC 128    // persistent blocks: 32 h-slices x 4 k-splits (<=148 SMs, all resident)
#define KS    4         // k-splits
#define KCH   256       // K per split

// ---------------- device-global scratch (no allocations allowed) ----------------
__device__ float g_wxB[(size_t)DIN * NT];                      // [d][n]  16 MB
__device__ float g_whT[(size_t)NT * HID];                      // [n][d]  16 MB
__device__ float g_pre[(size_t)TLEN * 4 * BATCH * HID];        // [t][g][b][h] 262 MB
__device__ float g_part[(size_t)KS * 4 * BATCH * HID];         // [ks][g][b*1024+h] 2 MB
__device__ float g_h2[2][BATCH * HID];                         // double-buffered h
__device__ volatile unsigned g_gen;                            // barrier generation
__device__ unsigned g_cnt;                                     // barrier arrive count

// quaternion cat tables: block (row-comp c, col-comp e) = sgn[c][e] * w[idx[c][e]]
__constant__ int   c_qidx[16] = {0,1,2,3,  1,0,3,2,  2,3,0,1,  3,2,1,0};
__constant__ float c_qsgn[16] = { 1.f, 1.f, 1.f, 1.f,
                                 -1.f, 1.f, 1.f,-1.f,
                                 -1.f,-1.f, 1.f, 1.f,
                                 -1.f, 1.f,-1.f, 1.f};

// ---------------- weight expansion ----------------
// wx, wh: [4 gates][4 comps][256][256]
// g_wxB[d*4096 + n] = qcat(wx[g])[d][h],   n = g*1024 + h
// g_whT[n*1024 + d] = qcat(wh[g])[d][h]
__global__ void expand_weights(const float* __restrict__ wx, const float* __restrict__ wh) {
    int i = blockIdx.x * 256 + threadIdx.x;          // 0 .. 2*4M-1
    int half = i >> 22;
    int o = i & 4194303;
    int d, n;
    if (half == 0) { d = o >> 12; n = o & 4095; }
    else           { n = o >> 10; d = o & 1023; }
    int g  = n >> 10, ho = n & 1023;
    int e  = ho >> 8, hh = ho & 255;
    int c  = d >> 8,  dd = d & 255;
    int q  = c * 4 + e;
    if (half == 0) g_wxB[o] = c_qsgn[q] * wx[((g * 4 + c_qidx[q]) * 256 + dd) * 256 + hh];
    else           g_whT[o] = c_qsgn[q] * wh[((g * 4 + c_qidx[q]) * 256 + dd) * 256 + hh];
}

__global__ void zero_state() {
    int i = blockIdx.x * 256 + threadIdx.x;
    if (i < BATCH * HID) g_h2[0][i] = 0.f;
}

// ---------------- input GEMM: pre = x @ wxB + bx ----------------
__global__ __launch_bounds__(256) void sgemm_pre(const float* __restrict__ x,
                                                 const float* __restrict__ bx) {
    __shared__ float As[8][128];
    __shared__ float Bs[8][128];
    const int bn = blockIdx.x;      // 0..31
    const int bm = blockIdx.y;      // 0..124
    const int tid = threadIdx.x;
    const int arow = tid >> 1, acol = (tid & 1) * 4;
    const int brow = tid >> 5, bcol = (tid & 31) * 4;
    const int ty = tid >> 4, tx = tid & 15;

    float acc[8][8];
#pragma unroll
    for (int i = 0; i < 8; i++)
#pragma unroll
        for (int j = 0; j < 8; j++) acc[i][j] = 0.f;

    const float* Ap = x + (size_t)(bm * 128 + arow) * DIN + acol;
    const float* Bp = g_wxB + (size_t)brow * NT + bn * 128 + bcol;

    for (int kt = 0; kt < DIN; kt += 8) {
        float4 a4 = *(const float4*)(Ap + kt);
        As[acol + 0][arow] = a4.x;
        As[acol + 1][arow] = a4.y;
        As[acol + 2][arow] = a4.z;
        As[acol + 3][arow] = a4.w;
        *(float4*)&Bs[brow][bcol] = *(const float4*)(Bp + (size_t)kt * NT);
        __syncthreads();
#pragma unroll
        for (int k = 0; k < 8; k++) {
            float4 a0 = *(const float4*)&As[k][ty * 8];
            float4 a1 = *(const float4*)&As[k][ty * 8 + 4];
            float4 b0 = *(const float4*)&Bs[k][tx * 8];
            float4 b1 = *(const float4*)&Bs[k][tx * 8 + 4];
            float ar[8] = {a0.x, a0.y, a0.z, a0.w, a1.x, a1.y, a1.z, a1.w};
            float br[8] = {b0.x, b0.y, b0.z, b0.w, b1.x, b1.y, b1.z, b1.w};
#pragma unroll
            for (int i = 0; i < 8; i++)
#pragma unroll
                for (int j = 0; j < 8; j++) acc[i][j] += ar[i] * br[j];
        }
        __syncthreads();
    }

#pragma unroll
    for (int i = 0; i < 8; i++) {
        int m = bm * 128 + ty * 8 + i;
        int t = m >> 5, b = m & 31;
#pragma unroll
        for (int j = 0; j < 8; j += 4) {
            int n = bn * 128 + tx * 8 + j;
            int g = n >> 10, h = n & 1023;
            float4 bb = *(const float4*)(bx + n);
            float4 o;
            o.x = acc[i][j + 0] + bb.x;
            o.y = acc[i][j + 1] + bb.y;
            o.z = acc[i][j + 2] + bb.z;
            o.w = acc[i][j + 3] + bb.w;
            *(float4*)&g_pre[(((size_t)t * 4 + g) * 32 + b) * 1024 + h] = o;
        }
    }
}

// ---------------- software grid barrier (all GRID_REC blocks co-resident) ----------------
__device__ __forceinline__ void grid_bar() {
    __syncthreads();
    if (threadIdx.x == 0) {
        __threadfence();                       // order prior stores before arrive
        unsigned gen = g_gen;
        if (atomicAdd(&g_cnt, 1) == GRID_REC - 1) {
            g_cnt = 0;
            __threadfence();
            g_gen = gen + 1;
        } else {
            while (g_gen == gen) {}
        }
        __threadfence();                       // acquire; also invalidates stale L1
    }
    __syncthreads();
}

// ---------------- persistent recurrence: 500 steps, 2 barriers/step ----------------
// block = (hs 0..31) x (ks 0..3). Phase1: partial GEMM (K chunk of 256) over
// 4 gates x 32 h x 32 batches; thread tile 4 gates x 4 batches (16 outputs).
// Phase2: 1 (b,h) element/thread: reduce 4 k-partials per gate, LSTM pointwise;
// c held in a register for the whole sequence; h double-buffered in global.
__global__ __launch_bounds__(256) void rec_persist(float* __restrict__ out) {
    const int blk = blockIdx.x;
    const int hs  = blk & 31;
    const int ks  = blk >> 5;
    const int k0  = ks * KCH;
    const int tid = threadIdx.x;
    const int rg  = tid >> 3;       // 0..31 = local h index
    const int bgi = tid & 7;        // batch group

    __shared__ float sh[32][68];    // h tile [batch][k-chunk], padded

    const float* w0 = g_whT + ((size_t)(0 * 1024 + hs * 32 + rg)) * 1024 + k0;
    const float* w1 = g_whT + ((size_t)(1 * 1024 + hs * 32 + rg)) * 1024 + k0;
    const float* w2 = g_whT + ((size_t)(2 * 1024 + hs * 32 + rg)) * 1024 + k0;
    const float* w3 = g_whT + ((size_t)(3 * 1024 + hs * 32 + rg)) * 1024 + k0;

    const int pidx = blk * 256 + tid;     // phase2 element: b*1024+h, exactly covers 32768
    float creg = 0.f;                     // cell state, register-resident

    for (int t = 0; t < TLEN; t++) {
        const float* hc = g_h2[t & 1];
        float acc[4][4];
#pragma unroll
        for (int g = 0; g < 4; g++)
#pragma unroll
            for (int i = 0; i < 4; i++) acc[g][i] = 0.f;

        for (int kc = 0; kc < KCH; kc += 64) {
            // cooperative h-tile load: 32x64 floats, 2 float4 per thread (L1-bypassed)
#pragma unroll
            for (int q = 0; q < 2; q++) {
                int f = tid + q * 256;
                int b = f >> 4, kk = (f & 15) * 4;
                float4 v = __ldcg((const float4*)(hc + b * 1024 + k0 + kc + kk));
                *(float4*)&sh[b][kk] = v;
            }
            __syncthreads();
#pragma unroll
            for (int kk = 0; kk < 64; kk += 4) {
                float4 a0 = *(const float4*)(w0 + kc + kk);
                float4 a1 = *(const float4*)(w1 + kc + kk);
                float4 a2 = *(const float4*)(w2 + kc + kk);
                float4 a3 = *(const float4*)(w3 + kc + kk);
                float4 h0 = *(const float4*)&sh[bgi +  0][kk];
                float4 h1 = *(const float4*)&sh[bgi +  8][kk];
                float4 h2 = *(const float4*)&sh[bgi + 16][kk];
                float4 h3 = *(const float4*)&sh[bgi + 24][kk];
#define DOT4(av, hv) (av.x * hv.x + av.y * hv.y + av.z * hv.z + av.w * hv.w)
                acc[0][0] += DOT4(a0, h0); acc[0][1] += DOT4(a0, h1);
                acc[0][2] += DOT4(a0, h2); acc[0][3] += DOT4(a0, h3);
                acc[1][0] += DOT4(a1, h0); acc[1][1] += DOT4(a1, h1);
                acc[1][2] += DOT4(a1, h2); acc[1][3] += DOT4(a1, h3);
                acc[2][0] += DOT4(a2, h0); acc[2][1] += DOT4(a2, h1);
                acc[2][2] += DOT4(a2, h2); acc[2][3] += DOT4(a2, h3);
                acc[3][0] += DOT4(a3, h0); acc[3][1] += DOT4(a3, h1);
                acc[3][2] += DOT4(a3, h2); acc[3][3] += DOT4(a3, h3);
#undef DOT4
            }
            __syncthreads();
        }
        // store partials: g_part[ks][g][b*1024 + h], h = hs*32+rg, b = bgi+8i
#pragma unroll
        for (int g = 0; g < 4; g++)
#pragma unroll
            for (int i = 0; i < 4; i++)
                g_part[((size_t)(ks * 4 + g) * 32 + bgi + 8 * i) * 1024 + hs * 32 + rg] = acc[g][i];

        grid_bar();

        // ---- phase 2: pointwise LSTM for one (b,h) ----
        {
            const float* pre_t = g_pre + (size_t)t * 4 * BATCH * HID;
            float gg[4];
#pragma unroll
            for (int g = 0; g < 4; g++) {
                float v = __ldcg(pre_t + (size_t)g * (BATCH * HID) + pidx);
#pragma unroll
                for (int s = 0; s < KS; s++)
                    v += __ldcg(&g_part[(size_t)(s * 4 + g) * (BATCH * HID) + pidx]);
                gg[g] = v;
            }
            float f = 1.f / (1.f + expf(-gg[0]));
            float i = 1.f / (1.f + expf(-gg[1]));
            float o = 1.f / (1.f + expf(-gg[2]));
            creg = i * tanhf(gg[3]) + f * creg;
            float hn = o * tanhf(creg);
            g_h2[(t + 1) & 1][pidx] = hn;
            out[(size_t)t * (BATCH * HID) + pidx] = hn;
        }

        grid_bar();
    }
}

// ---------------- launch: 4 graph nodes total ----------------
extern "C" void kernel_launch(void* const* d_in, const int* in_sizes, int n_in,
                              void* d_out, int out_size) {
    const float* x  = (const float*)d_in[0];   // [500][32][1024]
    const float* wx = (const float*)d_in[1];   // [4][4][256][256]
    const float* wh = (const float*)d_in[2];   // [4][4][256][256]
    const float* bx = (const float*)d_in[3];   // [4][1024]
    float* out = (float*)d_out;                // [500][32][1024]

    expand_weights<<<32768, 256>>>(wx, wh);
    zero_state<<<128, 256>>>();
    sgemm_pre<<<dim3(32, 125), 256>>>(x, bx);
    rec_persist<<<GRID_REC, 256>>>(out);
}

// round 7
// speedup vs baseline: 1.2843x; 1.2843x over previous
#include <cuda_runtime.h>
#include <math.h>
#include <stdint.h>

#define TLEN  500
#define BATCH 32
#define DIN   1024
#define HID   1024
#define NT    4096      // 4 gates * HID
#define GRID_REC 128    // persistent blocks, 1/SM, all co-resident
#define REC_THREADS 512

// smem layout (floats) for rec_persist
#define SW_F    (32 * 1024)          // weights: 32 rows (8 h x 4 gates) x 1024 k
#define SH_F    (32 * 260)           // h tile: 32 b x 256 k (+4 pad)
#define SRED_F  (384 * 8)            // k-split reduction: 3 groups x 128 thr x 8
#define SH_OFF  SW_F
#define SRED_OFF (SW_F + SH_F)
#define SMEM_BYTES ((SW_F + SH_F + SRED_F) * 4)

// ---------------- device-global scratch (no allocations allowed) ----------------
__device__ __align__(16) float g_wxB[(size_t)DIN * NT];               // [d][n] 16 MB
__device__ __align__(16) float g_whT[(size_t)NT * HID];               // [(h*4+g)][d] 16 MB
__device__ __align__(16) float g_pre[(size_t)TLEN * 4 * BATCH * HID]; // [t][g][b][h] 262 MB
__device__ __align__(16) float g_h2[2][BATCH * HID];                  // double-buffered h
__device__ volatile unsigned g_gen;
__device__ unsigned g_cnt;

// quaternion cat tables: block (row-comp c, col-comp e) = sgn[c][e] * w[idx[c][e]]
__constant__ int   c_qidx[16] = {0,1,2,3,  1,0,3,2,  2,3,0,1,  3,2,1,0};
__constant__ float c_qsgn[16] = { 1.f, 1.f, 1.f, 1.f,
                                 -1.f, 1.f, 1.f,-1.f,
                                 -1.f,-1.f, 1.f, 1.f,
                                 -1.f, 1.f,-1.f, 1.f};

// ---------------- weight expansion ----------------
// g_wxB[d*4096 + n] = qcat(wx[g])[d][h],  n = g*1024 + h
// g_whT[(h*4+g)*1024 + d] = qcat(wh[g])[d][h]   (row-per-output layout)
__global__ void expand_weights(const float* __restrict__ wx, const float* __restrict__ wh) {
    int i = blockIdx.x * 256 + threadIdx.x;          // 0 .. 2*4M-1
    int half = i >> 22;
    int o = i & 4194303;
    if (half == 0) {
        int d = o >> 12, n = o & 4095;
        int g = n >> 10, ho = n & 1023;
        int e = ho >> 8, hh = ho & 255;
        int c = d >> 8,  dd = d & 255;
        int q = c * 4 + e;
        g_wxB[o] = c_qsgn[q] * wx[((g * 4 + c_qidx[q]) * 256 + dd) * 256 + hh];
    } else {
        int h = o >> 12, g = (o >> 10) & 3, d = o & 1023;
        int e = h >> 8, hh = h & 255;
        int c = d >> 8, dd = d & 255;
        int q = c * 4 + e;
        g_whT[o] = c_qsgn[q] * wh[((g * 4 + c_qidx[q]) * 256 + dd) * 256 + hh];
    }
}

__global__ void zero_state() {
    int i = blockIdx.x * 256 + threadIdx.x;
    if (i < BATCH * HID) g_h2[0][i] = 0.f;
}

// ---------------- input GEMM: pre = x @ wxB + bx ----------------
__global__ __launch_bounds__(256) void sgemm_pre(const float* __restrict__ x,
                                                 const float* __restrict__ bx) {
    __shared__ float As[8][128];
    __shared__ float Bs[8][128];
    const int bn = blockIdx.x;      // 0..31
    const int bm = blockIdx.y;      // 0..124
    const int tid = threadIdx.x;
    const int arow = tid >> 1, acol = (tid & 1) * 4;
    const int brow = tid >> 5, bcol = (tid & 31) * 4;
    const int ty = tid >> 4, tx = tid & 15;

    float acc[8][8];
#pragma unroll
    for (int i = 0; i < 8; i++)
#pragma unroll
        for (int j = 0; j < 8; j++) acc[i][j] = 0.f;

    const float* Ap = x + (size_t)(bm * 128 + arow) * DIN + acol;
    const float* Bp = g_wxB + (size_t)brow * NT + bn * 128 + bcol;

    for (int kt = 0; kt < DIN; kt += 8) {
        float4 a4 = *(const float4*)(Ap + kt);
        As[acol + 0][arow] = a4.x;
        As[acol + 1][arow] = a4.y;
        As[acol + 2][arow] = a4.z;
        As[acol + 3][arow] = a4.w;
        *(float4*)&Bs[brow][bcol] = *(const float4*)(Bp + (size_t)kt * NT);
        __syncthreads();
#pragma unroll
        for (int k = 0; k < 8; k++) {
            float4 a0 = *(const float4*)&As[k][ty * 8];
            float4 a1 = *(const float4*)&As[k][ty * 8 + 4];
            float4 b0 = *(const float4*)&Bs[k][tx * 8];
            float4 b1 = *(const float4*)&Bs[k][tx * 8 + 4];
            float ar[8] = {a0.x, a0.y, a0.z, a0.w, a1.x, a1.y, a1.z, a1.w};
            float br[8] = {b0.x, b0.y, b0.z, b0.w, b1.x, b1.y, b1.z, b1.w};
#pragma unroll
            for (int i = 0; i < 8; i++)
#pragma unroll
                for (int j = 0; j < 8; j++) acc[i][j] += ar[i] * br[j];
        }
        __syncthreads();
    }

#pragma unroll
    for (int i = 0; i < 8; i++) {
        int m = bm * 128 + ty * 8 + i;
        int t = m >> 5, b = m & 31;
#pragma unroll
        for (int j = 0; j < 8; j += 4) {
            int n = bn * 128 + tx * 8 + j;
            int g = n >> 10, h = n & 1023;
            float4 bb = *(const float4*)(bx + n);
            float4 o;
            o.x = acc[i][j + 0] + bb.x;
            o.y = acc[i][j + 1] + bb.y;
            o.z = acc[i][j + 2] + bb.z;
            o.w = acc[i][j + 3] + bb.w;
            *(float4*)&g_pre[(((size_t)t * 4 + g) * 32 + b) * 1024 + h] = o;
        }
    }
}

// ---------------- software grid barrier ----------------
__device__ __forceinline__ void grid_bar() {
    __syncthreads();
    if (threadIdx.x == 0) {
        __threadfence();
        unsigned gen = g_gen;
        if (atomicAdd(&g_cnt, 1) == GRID_REC - 1) {
            g_cnt = 0;
            __threadfence();
            g_gen = gen + 1;
        } else {
            while (g_gen == gen) {}
        }
        __threadfence();
    }
    __syncthreads();
}

// ---------------- persistent recurrence: 1 barrier/step ----------------
// Block hs owns h in [hs*8, hs*8+8), all 4 gates, all 32 batches, full K.
// Threads: khalf = tid>>7 (k quarter), r = tid&127: b = r&31, hlp = r>>5.
// Thread tile: 2 h (hlp*2, hlp*2+1) x 4 gates, K-slice = 64 per 256-chunk.
// Weights resident in smem for the whole 500-step loop; gate preacts stay in
// registers (intra-block smem reduction over k-quarters); phase2: khalf==0
// threads own 2 (b,h) elements, c-state in registers, h double-buffered.
__global__ __launch_bounds__(REC_THREADS, 1) void rec_persist(float* __restrict__ out) {
    extern __shared__ float smem[];
    const int hs  = blockIdx.x;          // 0..127
    const int tid = threadIdx.x;
    const int khalf = tid >> 7;          // 0..3
    const int r   = tid & 127;
    const int b   = r & 31;
    const int hlp = r >> 5;              // 0..3
    const int lr0 = hlp * 8;             // first local weight row (2 h x 4 g)

    // ---- preload this block's 32 weight rows (8 h x 4 g) x 1024 k into smem ----
#pragma unroll
    for (int q = 0; q < 16; q++) {
        int i4 = tid + REC_THREADS * q;      // float4 index, 0..8191
        int lrr = i4 >> 8, kq = i4 & 255;
        *(float4*)&smem[lrr * 1024 + kq * 4] =
            *(const float4*)(g_whT + (size_t)(hs * 32 + lrr) * 1024 + kq * 4);
    }
    __syncthreads();

    float creg[2] = {0.f, 0.f};

    for (int t = 0; t < TLEN; t++) {
        const float* hc = g_h2[t & 1];

        // prefetch pre for phase2 (long-latency, overlapped with phase1)
        float pg[8];
        if (khalf == 0) {
            const float* pt = g_pre + (size_t)t * 131072 + b * 1024 + hs * 8 + hlp * 2;
#pragma unroll
            for (int g = 0; g < 4; g++) {
                pg[g * 2 + 0] = __ldcg(pt + g * 32768);
                pg[g * 2 + 1] = __ldcg(pt + g * 32768 + 1);
            }
        }

        float acc[2][4];
#pragma unroll
        for (int j = 0; j < 2; j++)
#pragma unroll
            for (int g = 0; g < 4; g++) acc[j][g] = 0.f;

        // prefetch h chunk 0
        float4 pf[4];
#pragma unroll
        for (int q = 0; q < 4; q++) {
            int f = tid + REC_THREADS * q;      // 0..2047 float4s
            pf[q] = __ldcg((const float4*)(hc + (f >> 6) * 1024 + (f & 63) * 4));
        }

        for (int c = 0; c < 4; c++) {
            const int k0 = c * 256;
            // stage chunk c
#pragma unroll
            for (int q = 0; q < 4; q++) {
                int f = tid + REC_THREADS * q;
                *(float4*)&smem[SH_OFF + (f >> 6) * 260 + (f & 63) * 4] = pf[q];
            }
            __syncthreads();
            // prefetch chunk c+1
            if (c < 3) {
#pragma unroll
                for (int q = 0; q < 4; q++) {
                    int f = tid + REC_THREADS * q;
                    pf[q] = __ldcg((const float4*)(hc + (f >> 6) * 1024 + (c + 1) * 256 + (f & 63) * 4));
                }
            }
            // compute this thread's 64-k slice of chunk c
            const float* shrow = &smem[SH_OFF + b * 260 + khalf * 64];
            const int wk = k0 + khalf * 64;
#pragma unroll
            for (int kk = 0; kk < 64; kk += 4) {
                float4 hv = *(const float4*)(shrow + kk);
#pragma unroll
                for (int j = 0; j < 2; j++)
#pragma unroll
                    for (int g = 0; g < 4; g++) {
                        float4 wv = *(const float4*)&smem[(lr0 + j * 4 + g) * 1024 + wk + kk];
                        acc[j][g] += hv.x * wv.x + hv.y * wv.y + hv.z * wv.z + hv.w * wv.w;
                    }
            }
            __syncthreads();
        }

        // ---- reduce k-quarters via smem ----
        if (khalf > 0) {
            float4* dst = (float4*)&smem[SRED_OFF + ((khalf - 1) * 128 + r) * 8];
            dst[0] = make_float4(acc[0][0], acc[0][1], acc[0][2], acc[0][3]);
            dst[1] = make_float4(acc[1][0], acc[1][1], acc[1][2], acc[1][3]);
        }
        __syncthreads();

        if (khalf == 0) {
#pragma unroll
            for (int q = 0; q < 3; q++) {
                const float4* src = (const float4*)&smem[SRED_OFF + (q * 128 + r) * 8];
                float4 v0 = src[0], v1 = src[1];
                acc[0][0] += v0.x; acc[0][1] += v0.y; acc[0][2] += v0.z; acc[0][3] += v0.w;
                acc[1][0] += v1.x; acc[1][1] += v1.y; acc[1][2] += v1.z; acc[1][3] += v1.w;
            }
            // ---- phase 2: pointwise LSTM for 2 (b,h) elements ----
#pragma unroll
            for (int j = 0; j < 2; j++) {
                float g0 = acc[j][0] + pg[0 * 2 + j];
                float g1 = acc[j][1] + pg[1 * 2 + j];
                float g2 = acc[j][2] + pg[2 * 2 + j];
                float g3 = acc[j][3] + pg[3 * 2 + j];
                float f = 1.f / (1.f + __expf(-g0));
                float i = 1.f / (1.f + __expf(-g1));
                float o = 1.f / (1.f + __expf(-g2));
                creg[j] = i * tanhf(g3) + f * creg[j];
                float hn = o * tanhf(creg[j]);
                int pidx = b * 1024 + hs * 8 + hlp * 2 + j;
                g_h2[(t + 1) & 1][pidx] = hn;
                out[(size_t)t * (BATCH * HID) + pidx] = hn;
            }
        }

        grid_bar();
    }
}

// ---------------- launch: 4 graph nodes ----------------
extern "C" void kernel_launch(void* const* d_in, const int* in_sizes, int n_in,
                              void* d_out, int out_size) {
    const float* x  = (const float*)d_in[0];   // [500][32][1024]
    const float* wx = (const float*)d_in[1];   // [4][4][256][256]
    const float* wh = (const float*)d_in[2];   // [4][4][256][256]
    const float* bx = (const float*)d_in[3];   // [4][1024]
    float* out = (float*)d_out;                // [500][32][1024]

    cudaFuncSetAttribute(rec_persist, cudaFuncAttributeMaxDynamicSharedMemorySize, SMEM_BYTES);

    expand_weights<<<32768, 256>>>(wx, wh);
    zero_state<<<128, 256>>>();
    sgemm_pre<<<dim3(32, 125), 256>>>(x, bx);
    rec_persist<<<GRID_REC, REC_THREADS, SMEM_BYTES>>>(out);
}

// round 8
// speedup vs baseline: 1.3236x; 1.0306x over previous
#include <cuda_runtime.h>
#include <math.h>
#include <stdint.h>

#define TLEN  500
#define BATCH 32
#define DIN   1024
#define HID   1024
#define NT    4096      // 4 gates * HID
#define GRID_REC 128    // persistent blocks, 1/SM, all co-resident
#define REC_THREADS 512

// rec_persist smem layout (floats)
#define WSTR  1028                   // weight row stride (pad: 2 rows 4 apart -> diff banks)
#define SW_F  (32 * WSTR)            // 32 rows (8 h x 4 gates) x 1024 k, padded
#define SH_F  (32 * 260)             // h tile: 32 b x 256 k (+4 pad)
#define SRED_F (3 * 128 * 8)         // k-split reduction: 3 groups x 128 thr x 8
#define SH_OFF  SW_F
#define SRED_OFF (SW_F + SH_F)
#define SMEM_BYTES ((SW_F + SH_F + SRED_F) * 4)

typedef unsigned long long ull;

__device__ __forceinline__ void ffma2(ull& d, ull a, ull b) {
    asm("fma.rn.f32x2 %0, %1, %2, %0;" : "+l"(d) : "l"(a), "l"(b));
}
__device__ __forceinline__ float2 u2f(ull u) {
    float2 r; asm("mov.b64 {%0,%1}, %2;" : "=f"(r.x), "=f"(r.y) : "l"(u)); return r;
}

// ---------------- device-global scratch ----------------
__device__ __align__(16) float g_wxB[(size_t)DIN * NT];               // [d][n] 16 MB
__device__ __align__(16) float g_whT[(size_t)NT * HID];               // [(h*4+g)][d] 16 MB
__device__ __align__(16) float g_pre[(size_t)TLEN * 4 * BATCH * HID]; // [t][g][b][h] 262 MB
__device__ __align__(16) float g_h2[2][BATCH * HID];                  // double-buffered h
__device__ volatile unsigned g_gen;
__device__ unsigned g_cnt;

// quaternion cat tables
__constant__ int   c_qidx[16] = {0,1,2,3,  1,0,3,2,  2,3,0,1,  3,2,1,0};
__constant__ float c_qsgn[16] = { 1.f, 1.f, 1.f, 1.f,
                                 -1.f, 1.f, 1.f,-1.f,
                                 -1.f,-1.f, 1.f, 1.f,
                                 -1.f, 1.f,-1.f, 1.f};

// ---------------- weight expansion ----------------
__global__ void expand_weights(const float* __restrict__ wx, const float* __restrict__ wh) {
    int i = blockIdx.x * 256 + threadIdx.x;
    int half = i >> 22;
    int o = i & 4194303;
    if (half == 0) {
        int d = o >> 12, n = o & 4095;
        int g = n >> 10, ho = n & 1023;
        int e = ho >> 8, hh = ho & 255;
        int c = d >> 8,  dd = d & 255;
        int q = c * 4 + e;
        g_wxB[o] = c_qsgn[q] * wx[((g * 4 + c_qidx[q]) * 256 + dd) * 256 + hh];
    } else {
        int h = o >> 12, g = (o >> 10) & 3, d = o & 1023;
        int e = h >> 8, hh = h & 255;
        int c = d >> 8, dd = d & 255;
        int q = c * 4 + e;
        g_whT[o] = c_qsgn[q] * wh[((g * 4 + c_qidx[q]) * 256 + dd) * 256 + hh];
    }
}

__global__ void zero_state() {
    int i = blockIdx.x * 256 + threadIdx.x;
    if (i < BATCH * HID) g_h2[0][i] = 0.f;
}

// ---------------- input GEMM: pre = x @ wxB + bx  (f32x2, n-paired) ----------------
// 128x128x8 tile, 256 threads, 8x8 microtile as 8 x 4 f32x2 pairs.
// A staged DUPLICATED in smem: Asd[k][2m..2m+1] = (a,a) -> b64 operand, zero packs.
__global__ __launch_bounds__(256) void sgemm_pre(const float* __restrict__ x,
                                                 const float* __restrict__ bx) {
    __shared__ float Asd[8][256];
    __shared__ float Bs[8][128];
    const int bn = blockIdx.x;      // 0..31
    const int bm = blockIdx.y;      // 0..124
    const int tid = threadIdx.x;
    const int arow = tid >> 1, acol = (tid & 1) * 4;
    const int brow = tid >> 5, bcol = (tid & 31) * 4;
    const int ty = tid >> 4, tx = tid & 15;

    ull acc[8][4];
#pragma unroll
    for (int i = 0; i < 8; i++)
#pragma unroll
        for (int j = 0; j < 4; j++) acc[i][j] = 0ull;

    const float* Ap = x + (size_t)(bm * 128 + arow) * DIN + acol;
    const float* Bp = g_wxB + (size_t)brow * NT + bn * 128 + bcol;

    for (int kt = 0; kt < DIN; kt += 8) {
        float4 a4 = *(const float4*)(Ap + kt);
        *(float2*)&Asd[acol + 0][2 * arow] = make_float2(a4.x, a4.x);
        *(float2*)&Asd[acol + 1][2 * arow] = make_float2(a4.y, a4.y);
        *(float2*)&Asd[acol + 2][2 * arow] = make_float2(a4.z, a4.z);
        *(float2*)&Asd[acol + 3][2 * arow] = make_float2(a4.w, a4.w);
        *(float4*)&Bs[brow][bcol] = *(const float4*)(Bp + (size_t)kt * NT);
        __syncthreads();
#pragma unroll
        for (int k = 0; k < 8; k++) {
            ulonglong2 a01 = *(const ulonglong2*)&Asd[k][ty * 16 + 0];
            ulonglong2 a23 = *(const ulonglong2*)&Asd[k][ty * 16 + 4];
            ulonglong2 a45 = *(const ulonglong2*)&Asd[k][ty * 16 + 8];
            ulonglong2 a67 = *(const ulonglong2*)&Asd[k][ty * 16 + 12];
            ulonglong2 b01 = *(const ulonglong2*)&Bs[k][tx * 8 + 0];
            ulonglong2 b23 = *(const ulonglong2*)&Bs[k][tx * 8 + 4];
            ull ar[8] = {a01.x, a01.y, a23.x, a23.y, a45.x, a45.y, a67.x, a67.y};
            ull br[4] = {b01.x, b01.y, b23.x, b23.y};
#pragma unroll
            for (int i = 0; i < 8; i++)
#pragma unroll
                for (int j = 0; j < 4; j++) ffma2(acc[i][j], ar[i], br[j]);
        }
        __syncthreads();
    }

    // epilogue: add bias, scatter to g_pre[t][g][b][h]
#pragma unroll
    for (int i = 0; i < 8; i++) {
        int m = bm * 128 + ty * 8 + i;
        int t = m >> 5, b = m & 31;
#pragma unroll
        for (int jp = 0; jp < 4; jp += 2) {
            int n = bn * 128 + tx * 8 + jp * 2;
            int g = n >> 10, h = n & 1023;
            float4 bb = *(const float4*)(bx + n);
            float2 p0 = u2f(acc[i][jp]);
            float2 p1 = u2f(acc[i][jp + 1]);
            float4 o;
            o.x = p0.x + bb.x;
            o.y = p0.y + bb.y;
            o.z = p1.x + bb.z;
            o.w = p1.y + bb.w;
            *(float4*)&g_pre[(((size_t)t * 4 + g) * 32 + b) * 1024 + h] = o;
        }
    }
}

// ---------------- software grid barrier ----------------
__device__ __forceinline__ void grid_bar() {
    __syncthreads();
    if (threadIdx.x == 0) {
        __threadfence();
        unsigned gen = g_gen;
        if (atomicAdd(&g_cnt, 1) == GRID_REC - 1) {
            g_cnt = 0;
            __threadfence();
            g_gen = gen + 1;
        } else {
            while (g_gen == gen) {}
        }
        __threadfence();
    }
    __syncthreads();
}

// ---------------- persistent recurrence (f32x2, k-paired) ----------------
// Block hs owns h in [hs*8, hs*8+8), all 4 gates, all 32 batches, full K.
// Warp w = tid>>5: ks = w>>2 (k-quarter of 64 per 256-chunk), whlp = w&3.
// Lane: hp = l>>4, b16 = l&15.  rg = whlp*2+hp = local h (0..7).
// Thread: 1 h x 4 gates x 2 batches (b16, b16+16), k-paired f32x2 accumulators.
// Weight LDS: 2 distinct rows/warp-instr, stride 1028 -> 1 phase.
// h LDS: 16 distinct rows x 16B, stride 260 -> 2 phases (minimum).
__global__ __launch_bounds__(REC_THREADS, 1) void rec_persist(float* __restrict__ out) {
    extern __shared__ float smem[];
    const int hs  = blockIdx.x;          // 0..127
    const int tid = threadIdx.x;
    const int w   = tid >> 5;
    const int ks  = w >> 2;              // 0..3
    const int whlp = w & 3;
    const int l   = tid & 31;
    const int hp  = l >> 4;
    const int b16 = l & 15;
    const int rg  = whlp * 2 + hp;       // local h 0..7
    const int b0  = b16, b1 = b16 + 16;
    const int rloc = whlp * 32 + l;      // 0..127 within k-group

    // ---- preload 32 weight rows x 1024 k into padded smem ----
#pragma unroll
    for (int q = 0; q < 16; q++) {
        int i4 = tid + REC_THREADS * q;      // 0..8191 float4s
        int lrr = i4 >> 8, kq = i4 & 255;
        *(float4*)&smem[lrr * WSTR + kq * 4] =
            *(const float4*)(g_whT + (size_t)(hs * 32 + lrr) * 1024 + kq * 4);
    }
    __syncthreads();

    float creg[2] = {0.f, 0.f};

    for (int t = 0; t < TLEN; t++) {
        const float* hc = g_h2[t & 1];

        // prefetch pre for phase2 (overlaps with phase1)
        float pg[4][2];
        if (ks == 0) {
            const float* pt = g_pre + (size_t)t * 131072 + hs * 8 + rg;
#pragma unroll
            for (int g = 0; g < 4; g++) {
                pg[g][0] = __ldcg(pt + g * 32768 + b0 * 1024);
                pg[g][1] = __ldcg(pt + g * 32768 + b1 * 1024);
            }
        }

        ull acc[4][2];                   // [gate][batch], each = (even-k sum, odd-k sum)
#pragma unroll
        for (int g = 0; g < 4; g++) { acc[g][0] = 0ull; acc[g][1] = 0ull; }

        // prefetch h chunk 0
        float4 pf[4];
#pragma unroll
        for (int q = 0; q < 4; q++) {
            int f = tid + REC_THREADS * q;
            pf[q] = __ldcg((const float4*)(hc + (f >> 6) * 1024 + (f & 63) * 4));
        }

        for (int c = 0; c < 4; c++) {
            // stage chunk c
#pragma unroll
            for (int q = 0; q < 4; q++) {
                int f = tid + REC_THREADS * q;
                *(float4*)&smem[SH_OFF + (f >> 6) * 260 + (f & 63) * 4] = pf[q];
            }
            __syncthreads();
            if (c < 3) {
#pragma unroll
                for (int q = 0; q < 4; q++) {
                    int f = tid + REC_THREADS * q;
                    pf[q] = __ldcg((const float4*)(hc + (f >> 6) * 1024 + (c + 1) * 256 + (f & 63) * 4));
                }
            }
            // compute 64-k slice of chunk c
            const float* wb  = &smem[rg * 4 * WSTR + c * 256 + ks * 64];
            const float* hr0 = &smem[SH_OFF + b0 * 260 + ks * 64];
            const float* hr1 = &smem[SH_OFF + b1 * 260 + ks * 64];
#pragma unroll
            for (int kk = 0; kk < 64; kk += 4) {
                ulonglong2 H0 = *(const ulonglong2*)(hr0 + kk);
                ulonglong2 H1 = *(const ulonglong2*)(hr1 + kk);
#pragma unroll
                for (int g = 0; g < 4; g++) {
                    ulonglong2 W = *(const ulonglong2*)(wb + g * WSTR + kk);
                    ffma2(acc[g][0], W.x, H0.x);
                    ffma2(acc[g][0], W.y, H0.y);
                    ffma2(acc[g][1], W.x, H1.x);
                    ffma2(acc[g][1], W.y, H1.y);
                }
            }
            __syncthreads();
        }

        // horizontal add of k-pairs
        float s[4][2];
#pragma unroll
        for (int g = 0; g < 4; g++) {
            float2 p0 = u2f(acc[g][0]); s[g][0] = p0.x + p0.y;
            float2 p1 = u2f(acc[g][1]); s[g][1] = p1.x + p1.y;
        }

        // ---- reduce k-quarters via smem ----
        if (ks > 0) {
            float4* dst = (float4*)&smem[SRED_OFF + ((ks - 1) * 128 + rloc) * 8];
            dst[0] = make_float4(s[0][0], s[1][0], s[2][0], s[3][0]);
            dst[1] = make_float4(s[0][1], s[1][1], s[2][1], s[3][1]);
        }
        __syncthreads();

        if (ks == 0) {
#pragma unroll
            for (int q = 0; q < 3; q++) {
                const float4* src = (const float4*)&smem[SRED_OFF + (q * 128 + rloc) * 8];
                float4 v0 = src[0], v1 = src[1];
                s[0][0] += v0.x; s[1][0] += v0.y; s[2][0] += v0.z; s[3][0] += v0.w;
                s[0][1] += v1.x; s[1][1] += v1.y; s[2][1] += v1.z; s[3][1] += v1.w;
            }
            // ---- phase 2: pointwise LSTM for 2 (b,h) cells ----
#pragma unroll
            for (int j = 0; j < 2; j++) {
                float g0 = s[0][j] + pg[0][j];
                float g1 = s[1][j] + pg[1][j];
                float g2 = s[2][j] + pg[2][j];
                float g3 = s[3][j] + pg[3][j];
                float f = 1.f / (1.f + __expf(-g0));
                float i = 1.f / (1.f + __expf(-g1));
                float o = 1.f / (1.f + __expf(-g2));
                creg[j] = i * tanhf(g3) + f * creg[j];
                float hn = o * tanhf(creg[j]);
                int b = (j == 0) ? b0 : b1;
                int pidx = b * 1024 + hs * 8 + rg;
                g_h2[(t + 1) & 1][pidx] = hn;
                out[(size_t)t * (BATCH * HID) + pidx] = hn;
            }
        }

        grid_bar();
    }
}

// ---------------- launch: 4 graph nodes ----------------
extern "C" void kernel_launch(void* const* d_in, const int* in_sizes, int n_in,
                              void* d_out, int out_size) {
    const float* x  = (const float*)d_in[0];   // [500][32][1024]
    const float* wx = (const float*)d_in[1];   // [4][4][256][256]
    const float* wh = (const float*)d_in[2];   // [4][4][256][256]
    const float* bx = (const float*)d_in[3];   // [4][1024]
    float* out = (float*)d_out;                // [500][32][1024]

    cudaFuncSetAttribute(rec_persist, cudaFuncAttributeMaxDynamicSharedMemorySize, SMEM_BYTES);

    expand_weights<<<32768, 256>>>(wx, wh);
    zero_state<<<128, 256>>>();
    sgemm_pre<<<dim3(32, 125), 256>>>(x, bx);
    rec_persist<<<GRID_REC, REC_THREADS, SMEM_BYTES>>>(out);
}

// round 10
// speedup vs baseline: 1.6507x; 1.2471x over previous
#include <cuda_runtime.h>
#include <math.h>
#include <stdint.h>

#define TLEN  500
#define BATCH 32
#define DIN   1024
#define HID   1024
#define NT    4096      // 4 gates * HID
#define GRID_REC 128
#define REC_THREADS 512

// ---------------- rec_persist smem layout (floats) ----------------
#define WSTR  1028
#define SW_F  (32 * WSTR)
#define SH_F  (32 * 260)
#define SRED_F (3 * 128 * 8)
#define SH_OFF  SW_F
#define SRED_OFF (SW_F + SH_F)
#define SMEM_BYTES ((SW_F + SH_F + SRED_F) * 4)

// ---------------- sgemm_pre_tc smem layout (floats) ----------------
#define SGA_STR 36                    // A row stride (conflict-free frag loads)
#define SGB_STR 136                   // B row stride (conflict-free frag loads)
#define SG_A_F  (128 * SGA_STR)       // 4608
#define SG_B_F  (32 * SGB_STR)        // 4352
#define SG_BUF_F (SG_A_F + 2 * SG_B_F)  // 13312 floats per buffer
#define SG_SMEM_BYTES (2 * SG_BUF_F * 4) // 106496 B double-buffered

typedef unsigned long long ull;

__device__ __forceinline__ void ffma2(ull& d, ull a, ull b) {
    asm("fma.rn.f32x2 %0, %1, %2, %0;" : "+l"(d) : "l"(a), "l"(b));
}
__device__ __forceinline__ float2 u2f(ull u) {
    float2 r; asm("mov.b64 {%0,%1}, %2;" : "=f"(r.x), "=f"(r.y) : "l"(u)); return r;
}
__device__ __forceinline__ uint32_t f2tf32(float v) {
    uint32_t u; asm("cvt.rna.tf32.f32 %0, %1;" : "=r"(u) : "f"(v)); return u;
}
__device__ __forceinline__ void mma_tf32(float* c, const uint32_t* a, const uint32_t* b) {
    asm("mma.sync.aligned.m16n8k8.row.col.f32.tf32.tf32.f32 "
        "{%0,%1,%2,%3},{%4,%5,%6,%7},{%8,%9},{%0,%1,%2,%3};"
        : "+f"(c[0]), "+f"(c[1]), "+f"(c[2]), "+f"(c[3])
        : "r"(a[0]), "r"(a[1]), "r"(a[2]), "r"(a[3]), "r"(b[0]), "r"(b[1]));
}
__device__ __forceinline__ void cpa16(uint32_t saddr, const void* g) {
    asm volatile("cp.async.cg.shared.global [%0], [%1], 16;" :: "r"(saddr), "l"(g));
}

// ---------------- device-global scratch ----------------
__device__ __align__(16) float g_wxB_hi[(size_t)DIN * NT];            // tf32 hi, 16 MB
__device__ __align__(16) float g_wxB_lo[(size_t)DIN * NT];            // tf32 lo, 16 MB
__device__ __align__(16) float g_whT[(size_t)NT * HID];               // [(h*4+g)][d] 16 MB
__device__ __align__(16) float g_pre[(size_t)TLEN * 4 * BATCH * HID]; // [t][g][b][h] 262 MB
__device__ __align__(16) float g_h2[2][BATCH * HID];
__device__ volatile unsigned g_gen;
__device__ unsigned g_cnt;

// quaternion cat tables
__constant__ int   c_qidx[16] = {0,1,2,3,  1,0,3,2,  2,3,0,1,  3,2,1,0};
__constant__ float c_qsgn[16] = { 1.f, 1.f, 1.f, 1.f,
                                 -1.f, 1.f, 1.f,-1.f,
                                 -1.f,-1.f, 1.f, 1.f,
                                 -1.f, 1.f,-1.f, 1.f};

// ---------------- weight expansion (+ tf32 hi/lo split for wx) ----------------
__global__ void expand_weights(const float* __restrict__ wx, const float* __restrict__ wh) {
    int i = blockIdx.x * 256 + threadIdx.x;
    int half = i >> 22;
    int o = i & 4194303;
    if (half == 0) {
        int d = o >> 12, n = o & 4095;
        int g = n >> 10, ho = n & 1023;
        int e = ho >> 8, hh = ho & 255;
        int c = d >> 8,  dd = d & 255;
        int q = c * 4 + e;
        float v = c_qsgn[q] * wx[((g * 4 + c_qidx[q]) * 256 + dd) * 256 + hh];
        uint32_t hb = f2tf32(v);
        float hf = __uint_as_float(hb);
        uint32_t lb = f2tf32(v - hf);
        g_wxB_hi[o] = hf;
        g_wxB_lo[o] = __uint_as_float(lb);
    } else {
        int h = o >> 12, g = (o >> 10) & 3, d = o & 1023;
        int e = h >> 8, hh = h & 255;
        int c = d >> 8, dd = d & 255;
        int q = c * 4 + e;
        g_whT[o] = c_qsgn[q] * wh[((g * 4 + c_qidx[q]) * 256 + dd) * 256 + hh];
    }
}

__global__ void zero_state() {
    int i = blockIdx.x * 256 + threadIdx.x;
    if (i < BATCH * HID) g_h2[0][i] = 0.f;
}

// ---------------- input GEMM on tensor cores: pre = x @ wxB + bx (3xTF32) ----------------
// Block 128(m)x128(n), K-step 32, 8 warps each m64xn32, cp.async double buffer.
__global__ __launch_bounds__(256) void sgemm_pre_tc(const float* __restrict__ x,
                                                    const float* __restrict__ bx) {
    extern __shared__ float sm[];
    const int bn = blockIdx.x;      // 0..31
    const int bm = blockIdx.y;      // 0..124
    const int tid = threadIdx.x;
    const int lane = tid & 31;
    const int wid = tid >> 5;
    const int wm = wid & 1;         // 0..1
    const int wn = wid >> 1;        // 0..3
    const int r  = lane >> 2;       // 0..7
    const int cq = lane & 3;        // 0..3

    float acc[4][4][4];
#pragma unroll
    for (int mi = 0; mi < 4; mi++)
#pragma unroll
        for (int ni = 0; ni < 4; ni++)
#pragma unroll
            for (int q = 0; q < 4; q++) acc[mi][ni][q] = 0.f;

    const uint32_t sm0 = (uint32_t)__cvta_generic_to_shared(sm);

    // tile loader: kt = k offset, buf = 0/1
    auto load_tile = [&](int kt, int buf) {
        uint32_t Ab = sm0 + (buf * SG_BUF_F) * 4;
        uint32_t Bh = Ab + SG_A_F * 4;
        uint32_t Bl = Bh + SG_B_F * 4;
        const float* xg = x + (size_t)(bm * 128) * DIN + kt;
        const float* wh = g_wxB_hi + (size_t)kt * NT + bn * 128;
        const float* wl = g_wxB_lo + (size_t)kt * NT + bn * 128;
#pragma unroll
        for (int q = 0; q < 4; q++) {
            int idx = tid + 256 * q;              // 0..1023
            int arow = idx >> 3, ac4 = idx & 7;   // A: 128 x 8 float4
            cpa16(Ab + (arow * SGA_STR + ac4 * 4) * 4, xg + (size_t)arow * DIN + ac4 * 4);
            int brow = idx >> 5, bc4 = idx & 31;  // B: 32 x 32 float4
            cpa16(Bh + (brow * SGB_STR + bc4 * 4) * 4, wh + (size_t)brow * NT + bc4 * 4);
            cpa16(Bl + (brow * SGB_STR + bc4 * 4) * 4, wl + (size_t)brow * NT + bc4 * 4);
        }
    };

    load_tile(0, 0);
    asm volatile("cp.async.commit_group;");

    for (int t = 0; t < 32; t++) {
        if (t < 31) {
            load_tile((t + 1) * 32, (t + 1) & 1);
            asm volatile("cp.async.commit_group;");
            asm volatile("cp.async.wait_group 1;");
        } else {
            asm volatile("cp.async.wait_group 0;");
        }
        __syncthreads();

        const float* As = sm + (t & 1) * SG_BUF_F;
        const float* Bh = As + SG_A_F;
        const float* Bl = Bh + SG_B_F;

#pragma unroll
        for (int kf = 0; kf < 4; kf++) {
            const int k0 = kf * 8;
            // B fragments (already tf32-rounded values)
            uint32_t bh[4][2], bl[4][2];
            const int brow = k0 + cq;
#pragma unroll
            for (int ni = 0; ni < 4; ni++) {
                int cb = wn * 32 + ni * 8 + r;
                bh[ni][0] = __float_as_uint(Bh[brow * SGB_STR + cb]);
                bh[ni][1] = __float_as_uint(Bh[(brow + 4) * SGB_STR + cb]);
                bl[ni][0] = __float_as_uint(Bl[brow * SGB_STR + cb]);
                bl[ni][1] = __float_as_uint(Bl[(brow + 4) * SGB_STR + cb]);
            }
#pragma unroll
            for (int mi = 0; mi < 4; mi++) {
                int rb = wm * 64 + mi * 16 + r;
                float v0 = As[rb * SGA_STR + k0 + cq];
                float v1 = As[(rb + 8) * SGA_STR + k0 + cq];
                float v2 = As[rb * SGA_STR + k0 + cq + 4];
                float v3 = As[(rb + 8) * SGA_STR + k0 + cq + 4];
                uint32_t ahi[4], alo[4];
                ahi[0] = f2tf32(v0); alo[0] = f2tf32(v0 - __uint_as_float(ahi[0]));
                ahi[1] = f2tf32(v1); alo[1] = f2tf32(v1 - __uint_as_float(ahi[1]));
                ahi[2] = f2tf32(v2); alo[2] = f2tf32(v2 - __uint_as_float(ahi[2]));
                ahi[3] = f2tf32(v3); alo[3] = f2tf32(v3 - __uint_as_float(ahi[3]));
#pragma unroll
                for (int ni = 0; ni < 4; ni++) {
                    mma_tf32(acc[mi][ni], ahi, bh[ni]);
                    mma_tf32(acc[mi][ni], ahi, bl[ni]);
                    mma_tf32(acc[mi][ni], alo, bh[ni]);
                }
            }
        }
        __syncthreads();
    }

    // epilogue: add bias, scatter to g_pre[t][g][b][h]
#pragma unroll
    for (int ni = 0; ni < 4; ni++) {
        int n0 = bn * 128 + wn * 32 + ni * 8 + 2 * cq;
        int g = n0 >> 10, h = n0 & 1023;
        float2 bb = *(const float2*)(bx + n0);
#pragma unroll
        for (int mi = 0; mi < 4; mi++) {
            int m0 = bm * 128 + wm * 64 + mi * 16 + r;
            int t0 = m0 >> 5, b0 = m0 & 31;
            int m1 = m0 + 8;
            int t1 = m1 >> 5, b1 = m1 & 31;
            float2 o0 = make_float2(acc[mi][ni][0] + bb.x, acc[mi][ni][1] + bb.y);
            float2 o1 = make_float2(acc[mi][ni][2] + bb.x, acc[mi][ni][3] + bb.y);
            *(float2*)&g_pre[(((size_t)t0 * 4 + g) * 32 + b0) * 1024 + h] = o0;
            *(float2*)&g_pre[(((size_t)t1 * 4 + g) * 32 + b1) * 1024 + h] = o1;
        }
    }
}

// ---------------- software grid barrier ----------------
__device__ __forceinline__ void grid_bar() {
    __syncthreads();
    if (threadIdx.x == 0) {
        __threadfence();
        unsigned gen = g_gen;
        if (atomicAdd(&g_cnt, 1) == GRID_REC - 1) {
            g_cnt = 0;
            __threadfence();
            g_gen = gen + 1;
        } else {
            while (g_gen == gen) {}
        }
        __threadfence();
    }
    __syncthreads();
}

// ---------------- persistent recurrence (f32x2, k-paired) — unchanged from R8 ----------------
__global__ __launch_bounds__(REC_THREADS, 1) void rec_persist(float* __restrict__ out) {
    extern __shared__ float smem[];
    const int hs  = blockIdx.x;
    const int tid = threadIdx.x;
    const int w   = tid >> 5;
    const int ks  = w >> 2;
    const int whlp = w & 3;
    const int l   = tid & 31;
    const int hp  = l >> 4;
    const int b16 = l & 15;
    const int rg  = whlp * 2 + hp;
    const int b0  = b16, b1 = b16 + 16;
    const int rloc = whlp * 32 + l;

#pragma unroll
    for (int q = 0; q < 16; q++) {
        int i4 = tid + REC_THREADS * q;
        int lrr = i4 >> 8, kq = i4 & 255;
        *(float4*)&smem[lrr * WSTR + kq * 4] =
            *(const float4*)(g_whT + (size_t)(hs * 32 + lrr) * 1024 + kq * 4);
    }
    __syncthreads();

    float creg[2] = {0.f, 0.f};

    for (int t = 0; t < TLEN; t++) {
        const float* hc = g_h2[t & 1];

        float pg[4][2];
        if (ks == 0) {
            const float* pt = g_pre + (size_t)t * 131072 + hs * 8 + rg;
#pragma unroll
            for (int g = 0; g < 4; g++) {
                pg[g][0] = __ldcg(pt + g * 32768 + b0 * 1024);
                pg[g][1] = __ldcg(pt + g * 32768 + b1 * 1024);
            }
        }

        ull acc[4][2];
#pragma unroll
        for (int g = 0; g < 4; g++) { acc[g][0] = 0ull; acc[g][1] = 0ull; }

        float4 pf[4];
#pragma unroll
        for (int q = 0; q < 4; q++) {
            int f = tid + REC_THREADS * q;
            pf[q] = __ldcg((const float4*)(hc + (f >> 6) * 1024 + (f & 63) * 4));
        }

        for (int c = 0; c < 4; c++) {
#pragma unroll
            for (int q = 0; q < 4; q++) {
                int f = tid + REC_THREADS * q;
                *(float4*)&smem[SH_OFF + (f >> 6) * 260 + (f & 63) * 4] = pf[q];
            }
            __syncthreads();
            if (c < 3) {
#pragma unroll
                for (int q = 0; q < 4; q++) {
                    int f = tid + REC_THREADS * q;
                    pf[q] = __ldcg((const float4*)(hc + (f >> 6) * 1024 + (c + 1) * 256 + (f & 63) * 4));
                }
            }
            const float* wb  = &smem[rg * 4 * WSTR + c * 256 + ks * 64];
            const float* hr0 = &smem[SH_OFF + b0 * 260 + ks * 64];
            const float* hr1 = &smem[SH_OFF + b1 * 260 + ks * 64];
#pragma unroll
            for (int kk = 0; kk < 64; kk += 4) {
                ulonglong2 H0 = *(const ulonglong2*)(hr0 + kk);
                ulonglong2 H1 = *(const ulonglong2*)(hr1 + kk);
#pragma unroll
                for (int g = 0; g < 4; g++) {
                    ulonglong2 W = *(const ulonglong2*)(wb + g * WSTR + kk);
                    ffma2(acc[g][0], W.x, H0.x);
                    ffma2(acc[g][0], W.y, H0.y);
                    ffma2(acc[g][1], W.x, H1.x);
                    ffma2(acc[g][1], W.y, H1.y);
                }
            }
            __syncthreads();
        }

        float s[4][2];
#pragma unroll
        for (int g = 0; g < 4; g++) {
            float2 p0 = u2f(acc[g][0]); s[g][0] = p0.x + p0.y;
            float2 p1 = u2f(acc[g][1]); s[g][1] = p1.x + p1.y;
        }

        if (ks > 0) {
            float4* dst = (float4*)&smem[SRED_OFF + ((ks - 1) * 128 + rloc) * 8];
            dst[0] = make_float4(s[0][0], s[1][0], s[2][0], s[3][0]);
            dst[1] = make_float4(s[0][1], s[1][1], s[2][1], s[3][1]);
        }
        __syncthreads();

        if (ks == 0) {
#pragma unroll
            for (int q = 0; q < 3; q++) {
                const float4* src = (const float4*)&smem[SRED_OFF + (q * 128 + rloc) * 8];
                float4 v0 = src[0], v1 = src[1];
                s[0][0] += v0.x; s[1][0] += v0.y; s[2][0] += v0.z; s[3][0] += v0.w;
                s[0][1] += v1.x; s[1][1] += v1.y; s[2][1] += v1.z; s[3][1] += v1.w;
            }
#pragma unroll
            for (int j = 0; j < 2; j++) {
                float g0 = s[0][j] + pg[0][j];
                float g1 = s[1][j] + pg[1][j];
                float g2 = s[2][j] + pg[2][j];
                float g3 = s[3][j] + pg[3][j];
                float f = 1.f / (1.f + __expf(-g0));
                float i = 1.f / (1.f + __expf(-g1));
                float o = 1.f / (1.f + __expf(-g2));
                creg[j] = i * tanhf(g3) + f * creg[j];
                float hn = o * tanhf(creg[j]);
                int b = (j == 0) ? b0 : b1;
                int pidx = b * 1024 + hs * 8 + rg;
                g_h2[(t + 1) & 1][pidx] = hn;
                out[(size_t)t * (BATCH * HID) + pidx] = hn;
            }
        }

        grid_bar();
    }
}

// ---------------- launch: 4 graph nodes ----------------
extern "C" void kernel_launch(void* const* d_in, const int* in_sizes, int n_in,
                              void* d_out, int out_size) {
    const float* x  = (const float*)d_in[0];   // [500][32][1024]
    const float* wx = (const float*)d_in[1];   // [4][4][256][256]
    const float* wh = (const float*)d_in[2];   // [4][4][256][256]
    const float* bx = (const float*)d_in[3];   // [4][1024]
    float* out = (float*)d_out;                // [500][32][1024]

    cudaFuncSetAttribute(sgemm_pre_tc, cudaFuncAttributeMaxDynamicSharedMemorySize, SG_SMEM_BYTES);
    cudaFuncSetAttribute(rec_persist, cudaFuncAttributeMaxDynamicSharedMemorySize, SMEM_BYTES);

    expand_weights<<<32768, 256>>>(wx, wh);
    zero_state<<<128, 256>>>();
    sgemm_pre_tc<<<dim3(32, 125), 256, SG_SMEM_BYTES>>>(x, bx);
    rec_persist<<<GRID_REC, REC_THREADS, SMEM_BYTES>>>(out);
}